// round 1
// baseline (speedup 1.0000x reference)
#include <cuda_runtime.h>
#include <cuda_bf16.h>
#include <math.h>

// PLIF neuron scan: x[B,T,C] -> spikes[B,T,C]
//   v = v*sigmoid(decay_param[c]) + x[b,t,c]; s = (v > 0.5); v -= 0.5*s
// B=128, T=256, C=2048. One thread owns 4 consecutive channels of one batch
// row; loads/stores are float4, coalesced across the warp. Recurrence is
// serial in t but loads are prefetched PF deep for MLP.

#define T_STEPS 256
#define C_CH    2048
#define GROUPS  (C_CH / 4)   // 512 float4 groups per channel dim
#define PF      8            // prefetch depth (power of 2)

__global__ __launch_bounds__(256, 4)
void plif_scan_kernel(const float* __restrict__ x,
                      const float* __restrict__ decay_param,
                      float* __restrict__ out)
{
    const int tid = blockIdx.x * blockDim.x + threadIdx.x;  // 0 .. 65535
    const int g   = tid & (GROUPS - 1);   // float4 group within C
    const int b   = tid >> 9;             // batch row (tid / 512)

    // Per-channel decay = sigmoid(decay_param). Computed once; IEEE expf to
    // avoid compounded drift over 256 multiplies.
    const float4 dp = reinterpret_cast<const float4*>(decay_param)[g];
    const float d0 = 1.0f / (1.0f + expf(-dp.x));
    const float d1 = 1.0f / (1.0f + expf(-dp.y));
    const float d2 = 1.0f / (1.0f + expf(-dp.z));
    const float d3 = 1.0f / (1.0f + expf(-dp.w));

    const float4* xp = reinterpret_cast<const float4*>(x)
                     + (size_t)b * (T_STEPS * GROUPS) + g;
    float4*       op = reinterpret_cast<float4*>(out)
                     + (size_t)b * (T_STEPS * GROUPS) + g;

    // Prime the prefetch ring: PF independent in-flight LDG.128 per thread.
    float4 buf[PF];
#pragma unroll
    for (int i = 0; i < PF; i++)
        buf[i] = __ldcs(xp + i * GROUPS);

    float v0 = 0.0f, v1 = 0.0f, v2 = 0.0f, v3 = 0.0f;

#pragma unroll 8
    for (int t = 0; t < T_STEPS; t++) {
        const float4 cur = buf[t & (PF - 1)];
        if (t + PF < T_STEPS)
            buf[t & (PF - 1)] = __ldcs(xp + (t + PF) * GROUPS);

        v0 = fmaf(v0, d0, cur.x);
        v1 = fmaf(v1, d1, cur.y);
        v2 = fmaf(v2, d2, cur.z);
        v3 = fmaf(v3, d3, cur.w);

        const float s0 = (v0 > 0.5f) ? 1.0f : 0.0f;
        const float s1 = (v1 > 0.5f) ? 1.0f : 0.0f;
        const float s2 = (v2 > 0.5f) ? 1.0f : 0.0f;
        const float s3 = (v3 > 0.5f) ? 1.0f : 0.0f;

        v0 = fmaf(s0, -0.5f, v0);
        v1 = fmaf(s1, -0.5f, v1);
        v2 = fmaf(s2, -0.5f, v2);
        v3 = fmaf(s3, -0.5f, v3);

        __stcs(op + t * GROUPS, make_float4(s0, s1, s2, s3));
    }
}

extern "C" void kernel_launch(void* const* d_in, const int* in_sizes, int n_in,
                              void* d_out, int out_size)
{
    const float* x  = (const float*)d_in[0];        // [128, 256, 2048]
    const float* dp = (const float*)d_in[1];        // [2048]
    float*       o  = (float*)d_out;                // [128, 256, 2048]

    const int total_threads = 128 * GROUPS;          // 65536
    const int block = 256;
    const int grid  = total_threads / block;         // 256
    plif_scan_kernel<<<grid, block>>>(x, dp, o);
}